// round 12
// baseline (speedup 1.0000x reference)
#include <cuda_runtime.h>

#define BN 16
#define CN 1024
#define TN 16
#define PN 360          // H*W
#define KN 120
#define OUTROWS 482     // 1 + 120 + 1 + 360
#define CT 64           // tile: c extent
#define PT 64           // tile: p extent
#define NCT (CN / CT)   // 16 c-tiles
#define NPT 6           // ceil(PN/PT)
#define NBLK (NPT * NCT)// 96 blocks per batch
#define PLANE (TN * PN) // 5760 floats per (b,c) plane
#define TS 68           // K1 tile row stride (floats)

// scratch (no allocations allowed)
__device__ float g_partial[BN][NCT][PN];
__device__ int   g_rank[BN][PN];
__device__ int   g_counter[BN];        // static-zeroed; re-zeroed by K2 each run

// ---------------------------------------------------------------------------
// K1: single fused pass over x[b, :, 0:2, :]  (round-8 proven geometry).
// Lanes 0-15 FMA frame-0 quads into registers; lanes 16-31 STS.128 frame-1
// quads into a [c][p] tile -> transposed STG.128 to out rows 122+p.
// Blocks (0,0,b) copy the two cls rows. The LAST block to finish partials for
// batch b (threadfence + atomic counter) becomes the closer: it reduces all
// partials and writes the exact stable descending rank (jax top_k tie-break:
// #greater + #equal-with-smaller-index; monotone softmax/max transforms can't
// change the ordering) for all 360 p of that batch.
// ---------------------------------------------------------------------------
__global__ void __launch_bounds__(256)
fused_kernel(const float* __restrict__ x, const float* __restrict__ cls,
             float* __restrict__ out) {
    __shared__ float tile[CT][TS];     // frame-1 only, [cc][pp]
    __shared__ float scls[CT];
    __shared__ float sacc[8][PT];
    __shared__ int   s_last;
    const int tid = threadIdx.x;
    const int b  = blockIdx.z;
    const int c0 = blockIdx.y * CT;
    const int p0 = blockIdx.x * PT;
    const float* xplane = x + ((size_t)b * CN + c0) * PLANE;

    if (tid < CT) scls[tid] = cls[(size_t)b * TN * CN + c0 + tid];
    __syncthreads();

    const int q  = tid & 31;
    const int wg = tid >> 5;
    const int f  = q >> 4;            // lane 0-15: frame 0, lane 16-31: frame 1
    const int pq = q & 15;
    const int p  = p0 + 4 * pq;
    const bool valid = (p < PN);

    float4 acc = make_float4(0.f, 0.f, 0.f, 0.f);
#pragma unroll
    for (int it = 0; it < 8; ++it) {               // cc = wg + it*8
        int cc = wg + it * 8;
        float4 v = make_float4(0.f, 0.f, 0.f, 0.f);
        if (valid)
            v = *(const float4*)(xplane + (size_t)cc * PLANE + f * PN + p);
        if (f == 0) {
            float s = scls[cc];
            acc.x = fmaf(s, v.x, acc.x);
            acc.y = fmaf(s, v.y, acc.y);
            acc.z = fmaf(s, v.z, acc.z);
            acc.w = fmaf(s, v.w, acc.w);
        } else {
            *(float4*)&tile[cc][4 * pq] = v;
        }
    }
    if (f == 0)
        *(float4*)&sacc[wg][4 * pq] = acc;

    // cls rows: out[b,0,:]=cls[b,0,:], out[b,121,:]=cls[b,1,:]
    if (blockIdx.x == 0 && blockIdx.y == 0) {
        const float4* c4 = (const float4*)(cls + (size_t)b * TN * CN);
        float4* o4 = (float4*)(out + (size_t)b * OUTROWS * CN);
        o4[tid] = c4[tid];                               // row 0
        o4[(size_t)121 * 256 + tid] = c4[256 + tid];     // row 121
    }
    __syncthreads();

    // partials for this (b, c-tile)
    if (tid < PT) {
        int pp = p0 + tid;
        if (pp < PN) {
            float a = 0.f;
#pragma unroll
            for (int w = 0; w < 8; ++w) a += sacc[w][tid];
            g_partial[b][blockIdx.y][pp] = a;
        }
    }

    // frame-1 transposed store
#pragma unroll
    for (int it = 0; it < 4; ++it) {
        int idx = tid + it * 256;
        int pl = idx >> 4, cq = idx & 15;
        int pp = p0 + pl;
        if (pp < PN) {
            float4 v;
            v.x = tile[4 * cq + 0][pl];
            v.y = tile[4 * cq + 1][pl];
            v.z = tile[4 * cq + 2][pl];
            v.w = tile[4 * cq + 3][pl];
            __stcs((float4*)(out + ((size_t)b * OUTROWS + 122 + pp) * CN + c0 + 4 * cq), v);
        }
    }

    // ---- closer-block rank ----
    __syncthreads();                   // all partial STGs issued by whole block
    __threadfence();                   // make them visible before counting
    if (tid == 0)
        s_last = (atomicAdd(&g_counter[b], 1) == NBLK - 1);
    __syncthreads();
    if (!s_last) return;

    // this is the unique closer for batch b: all 96 blocks' partials visible
    __shared__ float s[PN];
    for (int pp = tid; pp < PN; pp += 256) {
        float a = 0.f;
#pragma unroll
        for (int k = 0; k < NCT; ++k) a += g_partial[b][k][pp];
        s[pp] = a;
    }
    __syncthreads();
    for (int pp = tid; pp < PN; pp += 256) {
        float v = s[pp];
        int cnt = 0;
#pragma unroll 8
        for (int qq = 0; qq < PN; ++qq) {
            float sq = s[qq];
            cnt += (sq > v) || (sq == v && qq < pp);
        }
        g_rank[b][pp] = cnt;
    }
}

// ---------------------------------------------------------------------------
// K2: frame-0 scatter (round-8 proven; reads L2-resident after K1).
//   out[b, 1+rank[p], c] = x[b,c,0,p]   for rank[p] < K
// Also re-zeroes g_counter for the next graph replay.
// ---------------------------------------------------------------------------
__global__ void __launch_bounds__(256)
scatter0_kernel(const float* __restrict__ x, float* __restrict__ out) {
    __shared__ float tile[PT][CT + 1];
    __shared__ int   rk[PT];
    const int tid = threadIdx.x;
    const int b  = blockIdx.z;
    const int c0 = blockIdx.y * CT;
    const int p0 = blockIdx.x * PT;
    const float* xplane = x + ((size_t)b * CN + c0) * PLANE;   // t = 0

    if (blockIdx.x == 0 && blockIdx.y == 0 && tid == 0)
        g_counter[b] = 0;              // reset for next replay

    if (tid < PT) {
        int p = p0 + tid;
        rk[tid] = (p < PN) ? g_rank[b][p] : KN;
    }

#pragma unroll
    for (int it = 0; it < 4; ++it) {
        int idx = tid + it * 256;
        int cc = idx >> 4, pq = idx & 15;
        int p = p0 + 4 * pq;
        if (p < PN) {
            float4 v = *(const float4*)(xplane + (size_t)cc * PLANE + p);
            tile[4 * pq + 0][cc] = v.x;
            tile[4 * pq + 1][cc] = v.y;
            tile[4 * pq + 2][cc] = v.z;
            tile[4 * pq + 3][cc] = v.w;
        }
    }
    __syncthreads();

#pragma unroll
    for (int it = 0; it < 4; ++it) {
        int idx = tid + it * 256;
        int pl = idx >> 4, cq = idx & 15;
        int r = rk[pl];
        if (r >= KN) continue;
        float4 v;
        v.x = tile[pl][4 * cq + 0];
        v.y = tile[pl][4 * cq + 1];
        v.z = tile[pl][4 * cq + 2];
        v.w = tile[pl][4 * cq + 3];
        __stcs((float4*)(out + ((size_t)b * OUTROWS + 1 + r) * CN + c0 + 4 * cq), v);
    }
}

extern "C" void kernel_launch(void* const* d_in, const int* in_sizes, int n_in,
                              void* d_out, int out_size) {
    const float* x   = (const float*)d_in[0];   // [16,1024,16,12,30] f32
    const float* cls = (const float*)d_in[1];   // [16,16,1024] f32
    float* out = (float*)d_out;                 // [16,482,1024] f32

    fused_kernel<<<dim3(NPT, NCT, BN), 256>>>(x, cls, out);
    scatter0_kernel<<<dim3(NPT, NCT, BN), 256>>>(x, out);
}

// round 13
// speedup vs baseline: 2.5136x; 2.5136x over previous
#include <cuda_runtime.h>

#define BN 16
#define CN 1024
#define TN 16
#define PN 360          // H*W
#define KN 120
#define OUTROWS 482     // 1 + 120 + 1 + 360
#define CT 64           // tile: c extent
#define PT 64           // tile: p extent
#define NCT (CN / CT)   // 16 c-tiles
#define NPT 6           // ceil(PN/PT)
#define PLANE (TN * PN) // 5760 floats per (b,c) plane
#define TS 68           // K1 tile row stride (floats)

// scratch (no allocations allowed)
__device__ float g_partial[BN][NCT][PN];
__device__ int   g_rank[BN][PN];

// ---------------------------------------------------------------------------
// K1: single fused pass over x[b, :, 0:2, :]  (round-8 geometry).
// All 8 LDG.128 are issued into vv[8] BEFORE any consumer (front-batched MLP;
// launch_bounds(256,4) gives the 64-reg budget to hold them). Lanes 0-15 then
// FMA frame-0 quads; lanes 16-31 STS.128 frame-1 quads into a [c][p] tile ->
// transposed STG.128 to out rows 122+p. Blocks (0,0,b) copy the cls rows.
// ---------------------------------------------------------------------------
__global__ void __launch_bounds__(256, 4)
fused_kernel(const float* __restrict__ x, const float* __restrict__ cls,
             float* __restrict__ out) {
    __shared__ float tile[CT][TS];     // frame-1 only, [cc][pp]
    __shared__ float scls[CT];
    __shared__ float sacc[8][PT];
    const int tid = threadIdx.x;
    const int b  = blockIdx.z;
    const int c0 = blockIdx.y * CT;
    const int p0 = blockIdx.x * PT;
    const float* xplane = x + ((size_t)b * CN + c0) * PLANE;

    if (tid < CT) scls[tid] = cls[(size_t)b * TN * CN + c0 + tid];

    const int q  = tid & 31;
    const int wg = tid >> 5;
    const int f  = q >> 4;            // lane 0-15: frame 0, lane 16-31: frame 1
    const int pq = q & 15;
    const int p  = p0 + 4 * pq;
    const bool valid = (p < PN);

    // front-batched loads: 8 independent LDG.128 in flight
    float4 vv[8];
#pragma unroll
    for (int it = 0; it < 8; ++it) {               // cc = wg + it*8
        int cc = wg + it * 8;
        vv[it] = make_float4(0.f, 0.f, 0.f, 0.f);
        if (valid)
            vv[it] = *(const float4*)(xplane + (size_t)cc * PLANE + f * PN + p);
    }
    __syncthreads();                    // scls ready (overlaps load latency)

    if (f == 0) {
        float4 acc = make_float4(0.f, 0.f, 0.f, 0.f);
#pragma unroll
        for (int it = 0; it < 8; ++it) {
            float s = scls[wg + it * 8];
            acc.x = fmaf(s, vv[it].x, acc.x);
            acc.y = fmaf(s, vv[it].y, acc.y);
            acc.z = fmaf(s, vv[it].z, acc.z);
            acc.w = fmaf(s, vv[it].w, acc.w);
        }
        *(float4*)&sacc[wg][4 * pq] = acc;
    } else {
#pragma unroll
        for (int it = 0; it < 8; ++it)
            *(float4*)&tile[wg + it * 8][4 * pq] = vv[it];
    }

    // cls rows: out[b,0,:]=cls[b,0,:], out[b,121,:]=cls[b,1,:]
    if (blockIdx.x == 0 && blockIdx.y == 0) {
        const float4* c4 = (const float4*)(cls + (size_t)b * TN * CN);
        float4* o4 = (float4*)(out + (size_t)b * OUTROWS * CN);
        o4[tid] = c4[tid];                               // row 0
        o4[(size_t)121 * 256 + tid] = c4[256 + tid];     // row 121
    }
    __syncthreads();

    if (tid < PT) {
        int pp = p0 + tid;
        if (pp < PN) {
            float a = 0.f;
#pragma unroll
            for (int w = 0; w < 8; ++w) a += sacc[w][tid];
            g_partial[b][blockIdx.y][pp] = a;
        }
    }

#pragma unroll
    for (int it = 0; it < 4; ++it) {
        int idx = tid + it * 256;
        int pl = idx >> 4, cq = idx & 15;
        int pp = p0 + pl;
        if (pp < PN) {
            float4 v;
            v.x = tile[4 * cq + 0][pl];
            v.y = tile[4 * cq + 1][pl];
            v.z = tile[4 * cq + 2][pl];
            v.w = tile[4 * cq + 3][pl];
            __stcs((float4*)(out + ((size_t)b * OUTROWS + 122 + pp) * CN + c0 + 4 * cq), v);
        }
    }
}

// ---------------------------------------------------------------------------
// K2: reduce 16 partials -> score, exact stable descending rank (matches jax
// top_k tie-breaking: #greater + #equal-with-smaller-index). Monotone
// transforms (/sqrt(c), softmax, /frame_max) cannot change the ordering.
// ---------------------------------------------------------------------------
__global__ void __launch_bounds__(384)
rank_kernel(const float* __restrict__ cls, float* __restrict__ out) {
    const int b = blockIdx.x;
    const int p = threadIdx.x;
    __shared__ float s[PN];
    float v = 0.f;
    if (p < PN) {
#pragma unroll
        for (int k = 0; k < NCT; ++k) v += g_partial[b][k][p];
        s[p] = v;
    }
    __syncthreads();
    if (p < PN) {
        int cnt = 0;
#pragma unroll 8
        for (int q = 0; q < PN; ++q) {
            float sq = s[q];
            cnt += (sq > v) || (sq == v && q < p);
        }
        g_rank[b][p] = cnt;
    }
}

// ---------------------------------------------------------------------------
// K3: frame-0 scatter (reads L2-resident after K1), loads front-batched.
//   out[b, 1+rank[p], c] = x[b,c,0,p]   for rank[p] < K
// ---------------------------------------------------------------------------
__global__ void __launch_bounds__(256)
scatter0_kernel(const float* __restrict__ x, float* __restrict__ out) {
    __shared__ float tile[PT][CT + 1];
    __shared__ int   rk[PT];
    const int tid = threadIdx.x;
    const int b  = blockIdx.z;
    const int c0 = blockIdx.y * CT;
    const int p0 = blockIdx.x * PT;
    const float* xplane = x + ((size_t)b * CN + c0) * PLANE;   // t = 0

    // front-batched loads
    float4 vreg[4];
#pragma unroll
    for (int it = 0; it < 4; ++it) {
        int idx = tid + it * 256;
        int cc = idx >> 4, pq = idx & 15;
        int p = p0 + 4 * pq;
        vreg[it] = make_float4(0.f, 0.f, 0.f, 0.f);
        if (p < PN)
            vreg[it] = *(const float4*)(xplane + (size_t)cc * PLANE + p);
    }

    if (tid < PT) {
        int p = p0 + tid;
        rk[tid] = (p < PN) ? g_rank[b][p] : KN;
    }

#pragma unroll
    for (int it = 0; it < 4; ++it) {
        int idx = tid + it * 256;
        int cc = idx >> 4, pq = idx & 15;
        tile[4 * pq + 0][cc] = vreg[it].x;
        tile[4 * pq + 1][cc] = vreg[it].y;
        tile[4 * pq + 2][cc] = vreg[it].z;
        tile[4 * pq + 3][cc] = vreg[it].w;
    }
    __syncthreads();

#pragma unroll
    for (int it = 0; it < 4; ++it) {
        int idx = tid + it * 256;
        int pl = idx >> 4, cq = idx & 15;
        int r = rk[pl];
        if (r >= KN) continue;
        float4 v;
        v.x = tile[pl][4 * cq + 0];
        v.y = tile[pl][4 * cq + 1];
        v.z = tile[pl][4 * cq + 2];
        v.w = tile[pl][4 * cq + 3];
        __stcs((float4*)(out + ((size_t)b * OUTROWS + 1 + r) * CN + c0 + 4 * cq), v);
    }
}

extern "C" void kernel_launch(void* const* d_in, const int* in_sizes, int n_in,
                              void* d_out, int out_size) {
    const float* x   = (const float*)d_in[0];   // [16,1024,16,12,30] f32
    const float* cls = (const float*)d_in[1];   // [16,16,1024] f32
    float* out = (float*)d_out;                 // [16,482,1024] f32

    fused_kernel<<<dim3(NPT, NCT, BN), 256>>>(x, cls, out);
    rank_kernel<<<BN, 384>>>(cls, out);
    scatter0_kernel<<<dim3(NPT, NCT, BN), 256>>>(x, out);
}